// round 7
// baseline (speedup 1.0000x reference)
#include <cuda_runtime.h>
#include <cstdint>

#define NTOK   49
#define DIM    128
#define NWIN   4096
#define SCALE  0.17677669529663687f

// ---- global scratch (static __device__, no allocation) ----
__device__ float g_wq[49152];         // w_qkv, tf32 B-frag-packed
__device__ float g_wp[16384];         // w_proj, tf32 B-frag-packed
__device__ float g_xp[25690112];      // x, tf32 A-frag-packed (3136 64-row tiles)
__device__ float g_qkv[77070336];     // [200704][384]  Q(scaled)|K|V raw
__device__ float g_ao[25690112];      // [200704][128]  attention output raw
__device__ float g_aop[25690112];     // attention output, tf32 A-frag-packed

__device__ __forceinline__ uint32_t f2tf(float f) {
    uint32_t u;
    asm("cvt.rna.tf32.f32 %0, %1;" : "=r"(u) : "f"(f));
    return u;
}
__device__ __forceinline__ void mma8(float* c, const uint32_t* a, uint32_t b0, uint32_t b1) {
    asm("mma.sync.aligned.m16n8k8.row.col.f32.tf32.tf32.f32 "
        "{%0,%1,%2,%3},{%4,%5,%6,%7},{%8,%9},{%0,%1,%2,%3};"
        : "+f"(c[0]), "+f"(c[1]), "+f"(c[2]), "+f"(c[3])
        : "r"(a[0]), "r"(a[1]), "r"(a[2]), "r"(a[3]), "r"(b0), "r"(b1));
}
__device__ __forceinline__ void cpa16(uint32_t s, const void* g) {
    asm volatile("cp.async.cg.shared.global [%0], [%1], 16;" :: "r"(s), "l"(g));
}
__device__ __forceinline__ uint32_t smem_u32(const void* p) {
    uint32_t a;
    asm("{ .reg .u64 t; cvta.to.shared.u64 t, %1; cvt.u32.u64 %0, t; }" : "=r"(a) : "l"(p));
    return a;
}

// ---- prep: pack weights into tf32 B-fragment order ----
__global__ void prep_kernel(const float* __restrict__ wq, const float* __restrict__ wp) {
    int o = blockIdx.x * blockDim.x + threadIdx.x;        // 65536 total
    int oo = (o < 49152) ? o : o - 49152;
    int slot = oo & 3, gid = (oo >> 2) & 7, tig = (oo >> 5) & 3, kt = (oo >> 7) & 15;
    int nt = oo >> 11;
    int k = kt * 8 + tig + 4 * (slot & 1);
    int n = nt * 16 + gid + 8 * (slot >> 1);
    if (o < 49152) g_wq[oo] = __uint_as_float(f2tf(wq[k * 384 + n]));
    else           g_wp[oo] = __uint_as_float(f2tf(wp[k * 128 + n]));
}

// ---- pack_a: row-major [200704][128] -> tf32 A-frag-packed 64-row tiles ----
// uint4 u within tile: mt=u>>9, kt=(u>>5)&15, tig=(u>>3)&3, gid=u&7
// {a0,a1,a2,a3} = M[mt*16+gid+{0,8,0,8}][kt*8+tig+{0,0,4,4}]
__global__ void __launch_bounds__(256, 4)
pack_a(const float* __restrict__ src, float* __restrict__ dst) {
    __shared__ float sa[64 * 132];
    const int tid = threadIdx.x;
    const size_t row0 = (size_t)blockIdx.x * 64;
    const uint32_t su = smem_u32(sa);
    for (int i = tid; i < 2048; i += 256) {               // 64x128 float4s
        int r = i >> 5, c4 = i & 31;
        cpa16(su + (r * 132 + c4 * 4) * 4, src + (row0 + r) * DIM + c4 * 4);
    }
    asm volatile("cp.async.commit_group;\n\tcp.async.wait_group 0;");
    __syncthreads();
    float4* d4 = (float4*)(dst + (size_t)blockIdx.x * 8192);
    for (int u = tid; u < 2048; u += 256) {
        const int mt = u >> 9, kt = (u >> 5) & 15, tg = (u >> 3) & 3, gd = u & 7;
        const int r = mt * 16 + gd, c = kt * 8 + tg;
        float4 v;
        v.x = __uint_as_float(f2tf(sa[r * 132 + c]));
        v.y = __uint_as_float(f2tf(sa[(r + 8) * 132 + c]));
        v.z = __uint_as_float(f2tf(sa[r * 132 + c + 4]));
        v.w = __uint_as_float(f2tf(sa[(r + 8) * 132 + c + 4]));
        d4[u] = v;
    }
}

// ============================================================
// GEMM: C[64 x 128-slice] = A_packed * B_packed + bias, K=128
// MODE 0: A=g_xp, C=g_qkv (N=384, grid.y=3, Q slice scaled)
// MODE 1: A=g_aop, C=out (N=128)
// ============================================================
#define GS_B  8192
#define GS_BS 24576
#define GEMM_SMEMF 24704          // 98816 B

template<int MODE>
__global__ void __launch_bounds__(256, 2)
gemm_k128(const float* __restrict__ bias, float* __restrict__ Cext)
{
    extern __shared__ float sm[];
    float* bs = sm + GS_BS;
    const int tid = threadIdx.x, wid = tid >> 5, lane = tid & 31;
    const int gid = lane >> 2, tig = lane & 3;
    const uint32_t su = smem_u32(sm);

    const float* Ap   = ((MODE == 0) ? g_xp : g_aop) + (size_t)blockIdx.x * 8192;
    const float* Bp   = (MODE == 0) ? (g_wq + blockIdx.y * 16384) : g_wp;
    const float* bptr = (MODE == 0) ? (bias + blockIdx.y * 128)   : bias;
    const int    NO   = (MODE == 0) ? 384 : 128;
    const int    cb   = (MODE == 0) ? blockIdx.y * 128 : 0;
    const float  sc   = (MODE == 0 && blockIdx.y == 0) ? SCALE : 1.f;

    for (int i = tid; i < 2048; i += 256)                 // A packed 8192 floats
        cpa16(su + i * 16, Ap + i * 4);
    for (int i = tid; i < 4096; i += 256)                 // B packed 16384 floats
        cpa16(su + (GS_B + i * 4) * 4, Bp + i * 4);
    if (tid < 128) bs[tid] = bptr[tid];
    asm volatile("cp.async.commit_group;\n\tcp.async.wait_group 0;");
    __syncthreads();

    const int mw = wid & 1, nw = wid >> 1;
    float c[2][4][4];
#pragma unroll
    for (int f = 0; f < 2; f++)
#pragma unroll
        for (int j = 0; j < 4; j++)
#pragma unroll
            for (int e = 0; e < 4; e++) c[f][j][e] = 0.f;

    const uint4* As4 = (const uint4*)sm;
    const uint4* Bs4 = (const uint4*)(sm + GS_B);
#pragma unroll
    for (int kt = 0; kt < 16; kt++) {
        uint4 av0 = As4[((mw * 2 + 0) * 16 + kt) * 32 + tig * 8 + gid];
        uint4 av1 = As4[((mw * 2 + 1) * 16 + kt) * 32 + tig * 8 + gid];
        uint4 bv0 = Bs4[((nw * 2 + 0) * 16 + kt) * 32 + tig * 8 + gid];
        uint4 bv1 = Bs4[((nw * 2 + 1) * 16 + kt) * 32 + tig * 8 + gid];
        mma8(c[0][0], (const uint32_t*)&av0, bv0.x, bv0.y);
        mma8(c[0][1], (const uint32_t*)&av0, bv0.z, bv0.w);
        mma8(c[0][2], (const uint32_t*)&av0, bv1.x, bv1.y);
        mma8(c[0][3], (const uint32_t*)&av0, bv1.z, bv1.w);
        mma8(c[1][0], (const uint32_t*)&av1, bv0.x, bv0.y);
        mma8(c[1][1], (const uint32_t*)&av1, bv0.z, bv0.w);
        mma8(c[1][2], (const uint32_t*)&av1, bv1.x, bv1.y);
        mma8(c[1][3], (const uint32_t*)&av1, bv1.z, bv1.w);
    }

    float* C = (MODE == 0) ? g_qkv : Cext;
    const size_t arow0 = (size_t)blockIdx.x * 64;
#pragma unroll
    for (int f = 0; f < 2; f++) {
        const size_t r0 = arow0 + (mw * 2 + f) * 16 + gid;
#pragma unroll
        for (int j = 0; j < 4; j++) {
            const int cl = nw * 32 + j * 8 + 2 * tig;
            const float b0 = bs[cl], b1 = bs[cl + 1];
            const int cg = cb + cl;
            *(float2*)&C[r0 * NO + cg] =
                make_float2((c[f][j][0] + b0) * sc, (c[f][j][1] + b1) * sc);
            *(float2*)&C[(r0 + 8) * NO + cg] =
                make_float2((c[f][j][2] + b0) * sc, (c[f][j][3] + b1) * sc);
        }
    }
}

// ============================================================
// Attention: per-window, register softmax, shfl P-permute
// ============================================================
#define QS_LD 388
#define AS_RI 21728
#define AS_MK 24129
#define AS_BT 26530
#define ATTN_SMEMF 27206          // 108824 B

__global__ void __launch_bounds__(256, 2)
attn_kernel(const float* __restrict__ mask, const float* __restrict__ btab,
            const int* __restrict__ relidx)
{
    extern __shared__ float sm[];
    float* qs = sm;
    int*   ri = (int*)(sm + AS_RI);
    float* mk = sm + AS_MK;
    float* bt = sm + AS_BT;
    const int tid = threadIdx.x, wid = tid >> 5, lane = tid & 31;
    const int gid = lane >> 2, tig = lane & 3;
    const uint32_t su = smem_u32(sm);

    const int wb = blockIdx.x;
    const size_t row0 = (size_t)wb * NTOK;
    for (int i = tid; i < 4704; i += 256) {               // 49x384 float4
        int r = i / 96, c4 = i % 96;
        cpa16(su + (r * QS_LD + c4 * 4) * 4, g_qkv + (row0 + r) * 384 + c4 * 4);
    }
    for (int i = tid; i < 7 * QS_LD; i += 256) qs[49 * QS_LD + i] = 0.f;
    const int w = wb & 63;
    for (int i = tid; i < 2401; i += 256) { mk[i] = mask[w * 2401 + i]; ri[i] = relidx[i]; }
    for (int i = tid; i < 676; i += 256) bt[i] = btab[(i % 169) * 4 + (i / 169)];
    asm volatile("cp.async.commit_group;\n\tcp.async.wait_group 0;");
    __syncthreads();

    const int h = wid & 3, mt = wid >> 2;
#pragma unroll 1
    for (int sub = 0; sub < 2; sub++) {
        const int m0 = (mt * 2 + sub) * 16;
        const bool hiO = (m0 == 48);

        uint32_t aq[4][4];
#pragma unroll
        for (int kt = 0; kt < 4; kt++) {
            const float* p = qs + (m0 + gid) * QS_LD + h * 32 + kt * 8 + tig;
            aq[kt][0] = f2tf(p[0]);
            aq[kt][2] = f2tf(p[4]);
            aq[kt][1] = hiO ? 0u : f2tf(p[8 * QS_LD]);
            aq[kt][3] = hiO ? 0u : f2tf(p[8 * QS_LD + 4]);
        }
        float s_[7][4];
#pragma unroll
        for (int nt = 0; nt < 7; nt++) {
            float cc[4] = {0.f, 0.f, 0.f, 0.f};
#pragma unroll
            for (int kt = 0; kt < 4; kt++) {
                const float* kp = qs + (nt * 8 + gid) * QS_LD + 128 + h * 32 + kt * 8 + tig;
                mma8(cc, aq[kt], f2tf(kp[0]), f2tf(kp[4]));
            }
#pragma unroll
            for (int e = 0; e < 4; e++) s_[nt][e] = cc[e];
        }

        const int r0 = m0 + gid, r1 = r0 + 8;
        const bool v0 = r0 < NTOK, v1 = r1 < NTOK;
        float lo[7][2], hi[7][2];
        float mx0 = -1e30f, mx1 = -1e30f;
#pragma unroll
        for (int nt = 0; nt < 7; nt++)
#pragma unroll
            for (int s = 0; s < 2; s++) {
                const int cc = nt * 8 + 2 * tig + s;
                float a0 = -1e30f, a1 = -1e30f;
                if (cc < NTOK) {
                    if (v0) a0 = s_[nt][s]     + bt[h * 169 + ri[r0 * NTOK + cc]] + mk[r0 * NTOK + cc];
                    if (v1) a1 = s_[nt][2 + s] + bt[h * 169 + ri[r1 * NTOK + cc]] + mk[r1 * NTOK + cc];
                }
                lo[nt][s] = a0; hi[nt][s] = a1;
                mx0 = fmaxf(mx0, a0); mx1 = fmaxf(mx1, a1);
            }
        mx0 = fmaxf(mx0, __shfl_xor_sync(0xffffffffu, mx0, 1));
        mx0 = fmaxf(mx0, __shfl_xor_sync(0xffffffffu, mx0, 2));
        mx1 = fmaxf(mx1, __shfl_xor_sync(0xffffffffu, mx1, 1));
        mx1 = fmaxf(mx1, __shfl_xor_sync(0xffffffffu, mx1, 2));
        float s0 = 0.f, s1 = 0.f;
#pragma unroll
        for (int nt = 0; nt < 7; nt++)
#pragma unroll
            for (int s = 0; s < 2; s++) {
                float e0 = __expf(lo[nt][s] - mx0);
                float e1 = __expf(hi[nt][s] - mx1);
                lo[nt][s] = e0; hi[nt][s] = e1;
                s0 += e0; s1 += e1;
            }
        s0 += __shfl_xor_sync(0xffffffffu, s0, 1); s0 += __shfl_xor_sync(0xffffffffu, s0, 2);
        s1 += __shfl_xor_sync(0xffffffffu, s1, 1); s1 += __shfl_xor_sync(0xffffffffu, s1, 2);
        const float i0 = 1.f / s0, i1 = 1.f / s1;
#pragma unroll
        for (int nt = 0; nt < 7; nt++) {
            lo[nt][0] *= i0; lo[nt][1] *= i0;
            hi[nt][0] *= i1; hi[nt][1] *= i1;
        }

        float o[4][4];
#pragma unroll
        for (int nf = 0; nf < 4; nf++)
#pragma unroll
            for (int e = 0; e < 4; e++) o[nf][e] = 0.f;
        const int sA = tig >> 1, sB = sA + 2;
        const bool od = (tig & 1);
#pragma unroll
        for (int kt = 0; kt < 7; kt++) {
            float l0a = __shfl_sync(0xffffffffu, lo[kt][0], sA, 4);
            float l1a = __shfl_sync(0xffffffffu, lo[kt][1], sA, 4);
            float l0b = __shfl_sync(0xffffffffu, lo[kt][0], sB, 4);
            float l1b = __shfl_sync(0xffffffffu, lo[kt][1], sB, 4);
            float h0a = __shfl_sync(0xffffffffu, hi[kt][0], sA, 4);
            float h1a = __shfl_sync(0xffffffffu, hi[kt][1], sA, 4);
            float h0b = __shfl_sync(0xffffffffu, hi[kt][0], sB, 4);
            float h1b = __shfl_sync(0xffffffffu, hi[kt][1], sB, 4);
            uint32_t ap[4];
            ap[0] = f2tf(od ? l1a : l0a);
            ap[1] = f2tf(od ? h1a : h0a);
            ap[2] = f2tf(od ? l1b : l0b);
            ap[3] = f2tf(od ? h1b : h0b);
#pragma unroll
            for (int nf = 0; nf < 4; nf++) {
                const float* vpt = qs + (kt * 8 + tig) * QS_LD + 256 + h * 32 + nf * 8 + gid;
                mma8(o[nf], ap, f2tf(vpt[0]), f2tf(vpt[4 * QS_LD]));
            }
        }
#pragma unroll
        for (int nf = 0; nf < 4; nf++) {
            const int col = h * 32 + nf * 8 + 2 * tig;
            if (v0) *(float2*)&g_ao[(row0 + r0) * DIM + col] = make_float2(o[nf][0], o[nf][1]);
            if (v1) *(float2*)&g_ao[(row0 + r1) * DIM + col] = make_float2(o[nf][2], o[nf][3]);
        }
    }
}

extern "C" void kernel_launch(void* const* d_in, const int* in_sizes, int n_in,
                              void* d_out, int out_size)
{
    const float* x      = (const float*)d_in[0];
    const float* mask   = (const float*)d_in[1];
    const float* w_qkv  = (const float*)d_in[2];
    const float* b_qkv  = (const float*)d_in[3];
    const float* btab   = (const float*)d_in[4];
    const float* w_proj = (const float*)d_in[5];
    const float* b_proj = (const float*)d_in[6];
    const int*   relidx = (const int*)  d_in[7];
    float* out = (float*)d_out;

    float* d_xp;  cudaGetSymbolAddress((void**)&d_xp,  g_xp);
    float* d_ao;  cudaGetSymbolAddress((void**)&d_ao,  g_ao);
    float* d_aop; cudaGetSymbolAddress((void**)&d_aop, g_aop);

    cudaFuncSetAttribute(gemm_k128<0>, cudaFuncAttributeMaxDynamicSharedMemorySize,
                         GEMM_SMEMF * 4);
    cudaFuncSetAttribute(gemm_k128<1>, cudaFuncAttributeMaxDynamicSharedMemorySize,
                         GEMM_SMEMF * 4);
    cudaFuncSetAttribute(attn_kernel, cudaFuncAttributeMaxDynamicSharedMemorySize,
                         ATTN_SMEMF * 4);

    prep_kernel<<<128, 512>>>(w_qkv, w_proj);
    pack_a<<<3136, 256>>>(x, d_xp);
    gemm_k128<0><<<dim3(3136, 3), 256, GEMM_SMEMF * 4>>>(b_qkv, nullptr);
    attn_kernel<<<NWIN, 256, ATTN_SMEMF * 4>>>(mask, btab, relidx);
    pack_a<<<3136, 256>>>(d_ao, d_aop);
    gemm_k128<1><<<dim3(3136, 1), 256, GEMM_SMEMF * 4>>>(b_proj, out);
}

// round 8
// speedup vs baseline: 1.0197x; 1.0197x over previous
#include <cuda_runtime.h>
#include <cstdint>

#define NTOK   49
#define DIM    128
#define NWIN   4096
#define SCALE  0.17677669529663687f

// ---- global scratch (static __device__, no allocation) ----
__device__ float g_wq[49152];         // w_qkv, tf32 B-frag-packed
__device__ float g_wp[16384];         // w_proj, tf32 B-frag-packed
__device__ float g_qkv[77070336];     // [200704][384]  Q(scaled)|K|V raw
__device__ float g_ao[25690112];      // [200704][128]  attention output raw

__device__ __forceinline__ uint32_t f2tf(float f) {
    uint32_t u;
    asm("cvt.rna.tf32.f32 %0, %1;" : "=r"(u) : "f"(f));
    return u;
}
__device__ __forceinline__ void mma8(float* c, const uint32_t* a, uint32_t b0, uint32_t b1) {
    asm("mma.sync.aligned.m16n8k8.row.col.f32.tf32.tf32.f32 "
        "{%0,%1,%2,%3},{%4,%5,%6,%7},{%8,%9},{%0,%1,%2,%3};"
        : "+f"(c[0]), "+f"(c[1]), "+f"(c[2]), "+f"(c[3])
        : "r"(a[0]), "r"(a[1]), "r"(a[2]), "r"(a[3]), "r"(b0), "r"(b1));
}
__device__ __forceinline__ void cpa16(uint32_t s, const void* g) {
    asm volatile("cp.async.cg.shared.global [%0], [%1], 16;" :: "r"(s), "l"(g));
}
__device__ __forceinline__ uint32_t smem_u32(const void* p) {
    uint32_t a;
    asm("{ .reg .u64 t; cvta.to.shared.u64 t, %1; cvt.u32.u64 %0, t; }" : "=r"(a) : "l"(p));
    return a;
}

// ---- prep: pack weights into tf32 B-fragment order ----
__global__ void prep_kernel(const float* __restrict__ wq, const float* __restrict__ wp) {
    int o = blockIdx.x * blockDim.x + threadIdx.x;        // 65536 total
    int oo = (o < 49152) ? o : o - 49152;
    int slot = oo & 3, gid = (oo >> 2) & 7, tig = (oo >> 5) & 3, kt = (oo >> 7) & 15;
    int nt = oo >> 11;
    int k = kt * 8 + tig + 4 * (slot & 1);
    int n = nt * 16 + gid + 8 * (slot >> 1);
    if (o < 49152) g_wq[oo] = __uint_as_float(f2tf(wq[k * 384 + n]));
    else           g_wp[oo] = __uint_as_float(f2tf(wp[k * 128 + n]));
}

// ============================================================
// GEMM: C[64 x 128-slice] = A * B_packed + bias, K=128
//   A raw 64x128 loaded once, repacked in-smem to tf32 A-frags.
// MODE 0: A=x,    C=g_qkv (N=384, grid.y=3, Q slice scaled)
// MODE 1: A=g_ao, C=out   (N=128)
// ============================================================
#define GA_LD 132
#define GS_B  8448                 // raw A 64*132
#define GS_BS 24832
#define GEMM_SMEMF 24960           // 99840 B -> 2 blocks/SM

template<int MODE>
__global__ void __launch_bounds__(256, 2)
gemm_k128(const float* __restrict__ Aext, const float* __restrict__ bias,
          float* __restrict__ Cext)
{
    extern __shared__ float sm[];
    float* bs = sm + GS_BS;
    const int tid = threadIdx.x, wid = tid >> 5, lane = tid & 31;
    const int gid = lane >> 2, tig = lane & 3;
    const uint32_t su = smem_u32(sm);

    const float* A    = (MODE == 0) ? Aext : g_ao;
    const float* Bp   = (MODE == 0) ? (g_wq + blockIdx.y * 16384) : g_wp;
    const float* bptr = (MODE == 0) ? (bias + blockIdx.y * 128)   : bias;
    const int    NO   = (MODE == 0) ? 384 : 128;
    const int    cb   = (MODE == 0) ? blockIdx.y * 128 : 0;
    const float  sc   = (MODE == 0 && blockIdx.y == 0) ? SCALE : 1.f;

    const size_t arow0 = (size_t)blockIdx.x * 64;
    for (int i = tid; i < 2048; i += 256) {               // raw A 64x128
        int r = i >> 5, c4 = i & 31;
        cpa16(su + (r * GA_LD + c4 * 4) * 4, A + (arow0 + r) * DIM + c4 * 4);
    }
    for (int i = tid; i < 4096; i += 256)                 // B packed 16384 floats
        cpa16(su + (GS_B + i * 4) * 4, Bp + i * 4);
    if (tid < 128) bs[tid] = bptr[tid];
    asm volatile("cp.async.commit_group;\n\tcp.async.wait_group 0;");
    __syncthreads();

    // ---- one-time in-smem A repack (register-staged, conflict-free) ----
    // uint4 u: mt=u>>9, kt=(u>>5)&15, tg=(u>>3)&3, gd=u&7
    float4 stg[8];
#pragma unroll
    for (int j = 0; j < 8; j++) {
        const int u = tid + 256 * j;
        const int mt = u >> 9, kt = (u >> 5) & 15, tg = (u >> 3) & 3, gd = u & 7;
        const int r = mt * 16 + gd, c = kt * 8 + tg;
        stg[j].x = __uint_as_float(f2tf(sm[r * GA_LD + c]));
        stg[j].y = __uint_as_float(f2tf(sm[(r + 8) * GA_LD + c]));
        stg[j].z = __uint_as_float(f2tf(sm[r * GA_LD + c + 4]));
        stg[j].w = __uint_as_float(f2tf(sm[(r + 8) * GA_LD + c + 4]));
    }
    __syncthreads();
    {
        float4* As4w = (float4*)sm;
#pragma unroll
        for (int j = 0; j < 8; j++) As4w[tid + 256 * j] = stg[j];
    }
    __syncthreads();

    const int mw = wid & 1, nw = wid >> 1;
    float c[2][4][4];
#pragma unroll
    for (int f = 0; f < 2; f++)
#pragma unroll
        for (int j = 0; j < 4; j++)
#pragma unroll
            for (int e = 0; e < 4; e++) c[f][j][e] = 0.f;

    const uint4* As4 = (const uint4*)sm;
    const uint4* Bs4 = (const uint4*)(sm + GS_B);
#pragma unroll
    for (int kt = 0; kt < 16; kt++) {
        uint4 av0 = As4[((mw * 2 + 0) * 16 + kt) * 32 + tig * 8 + gid];
        uint4 av1 = As4[((mw * 2 + 1) * 16 + kt) * 32 + tig * 8 + gid];
        uint4 bv0 = Bs4[((nw * 2 + 0) * 16 + kt) * 32 + tig * 8 + gid];
        uint4 bv1 = Bs4[((nw * 2 + 1) * 16 + kt) * 32 + tig * 8 + gid];
        mma8(c[0][0], (const uint32_t*)&av0, bv0.x, bv0.y);
        mma8(c[0][1], (const uint32_t*)&av0, bv0.z, bv0.w);
        mma8(c[0][2], (const uint32_t*)&av0, bv1.x, bv1.y);
        mma8(c[0][3], (const uint32_t*)&av0, bv1.z, bv1.w);
        mma8(c[1][0], (const uint32_t*)&av1, bv0.x, bv0.y);
        mma8(c[1][1], (const uint32_t*)&av1, bv0.z, bv0.w);
        mma8(c[1][2], (const uint32_t*)&av1, bv1.x, bv1.y);
        mma8(c[1][3], (const uint32_t*)&av1, bv1.z, bv1.w);
    }

    float* C = (MODE == 0) ? g_qkv : Cext;
#pragma unroll
    for (int f = 0; f < 2; f++) {
        const size_t r0 = arow0 + (mw * 2 + f) * 16 + gid;
#pragma unroll
        for (int j = 0; j < 4; j++) {
            const int cl = nw * 32 + j * 8 + 2 * tig;
            const float b0 = bs[cl], b1 = bs[cl + 1];
            const int cg = cb + cl;
            *(float2*)&C[r0 * NO + cg] =
                make_float2((c[f][j][0] + b0) * sc, (c[f][j][1] + b1) * sc);
            *(float2*)&C[(r0 + 8) * NO + cg] =
                make_float2((c[f][j][2] + b0) * sc, (c[f][j][3] + b1) * sc);
        }
    }
}

// ============================================================
// Attention: per-window, register softmax, shfl P-permute
// ============================================================
#define QS_LD 388
#define AS_RI 21728
#define AS_MK 24129
#define AS_BT 26530
#define ATTN_SMEMF 27206          // 108824 B

__global__ void __launch_bounds__(256, 2)
attn_kernel(const float* __restrict__ mask, const float* __restrict__ btab,
            const int* __restrict__ relidx)
{
    extern __shared__ float sm[];
    float* qs = sm;
    int*   ri = (int*)(sm + AS_RI);
    float* mk = sm + AS_MK;
    float* bt = sm + AS_BT;
    const int tid = threadIdx.x, wid = tid >> 5, lane = tid & 31;
    const int gid = lane >> 2, tig = lane & 3;
    const uint32_t su = smem_u32(sm);

    const int wb = blockIdx.x;
    const size_t row0 = (size_t)wb * NTOK;
    for (int i = tid; i < 4704; i += 256) {               // 49x384 float4
        int r = i / 96, c4 = i % 96;
        cpa16(su + (r * QS_LD + c4 * 4) * 4, g_qkv + (row0 + r) * 384 + c4 * 4);
    }
    for (int i = tid; i < 7 * QS_LD; i += 256) qs[49 * QS_LD + i] = 0.f;
    const int w = wb & 63;
    for (int i = tid; i < 2401; i += 256) { mk[i] = mask[w * 2401 + i]; ri[i] = relidx[i]; }
    for (int i = tid; i < 676; i += 256) bt[i] = btab[(i % 169) * 4 + (i / 169)];
    asm volatile("cp.async.commit_group;\n\tcp.async.wait_group 0;");
    __syncthreads();

    const int h = wid & 3, mt = wid >> 2;
#pragma unroll 1
    for (int sub = 0; sub < 2; sub++) {
        const int m0 = (mt * 2 + sub) * 16;
        const bool hiO = (m0 == 48);

        uint32_t aq[4][4];
#pragma unroll
        for (int kt = 0; kt < 4; kt++) {
            const float* p = qs + (m0 + gid) * QS_LD + h * 32 + kt * 8 + tig;
            aq[kt][0] = f2tf(p[0]);
            aq[kt][2] = f2tf(p[4]);
            aq[kt][1] = hiO ? 0u : f2tf(p[8 * QS_LD]);
            aq[kt][3] = hiO ? 0u : f2tf(p[8 * QS_LD + 4]);
        }
        float s_[7][4];
#pragma unroll
        for (int nt = 0; nt < 7; nt++) {
            float cc[4] = {0.f, 0.f, 0.f, 0.f};
#pragma unroll
            for (int kt = 0; kt < 4; kt++) {
                const float* kp = qs + (nt * 8 + gid) * QS_LD + 128 + h * 32 + kt * 8 + tig;
                mma8(cc, aq[kt], f2tf(kp[0]), f2tf(kp[4]));
            }
#pragma unroll
            for (int e = 0; e < 4; e++) s_[nt][e] = cc[e];
        }

        const int r0 = m0 + gid, r1 = r0 + 8;
        const bool v0 = r0 < NTOK, v1 = r1 < NTOK;
        float lo[7][2], hi[7][2];
        float mx0 = -1e30f, mx1 = -1e30f;
#pragma unroll
        for (int nt = 0; nt < 7; nt++)
#pragma unroll
            for (int s = 0; s < 2; s++) {
                const int cc = nt * 8 + 2 * tig + s;
                float a0 = -1e30f, a1 = -1e30f;
                if (cc < NTOK) {
                    if (v0) a0 = s_[nt][s]     + bt[h * 169 + ri[r0 * NTOK + cc]] + mk[r0 * NTOK + cc];
                    if (v1) a1 = s_[nt][2 + s] + bt[h * 169 + ri[r1 * NTOK + cc]] + mk[r1 * NTOK + cc];
                }
                lo[nt][s] = a0; hi[nt][s] = a1;
                mx0 = fmaxf(mx0, a0); mx1 = fmaxf(mx1, a1);
            }
        mx0 = fmaxf(mx0, __shfl_xor_sync(0xffffffffu, mx0, 1));
        mx0 = fmaxf(mx0, __shfl_xor_sync(0xffffffffu, mx0, 2));
        mx1 = fmaxf(mx1, __shfl_xor_sync(0xffffffffu, mx1, 1));
        mx1 = fmaxf(mx1, __shfl_xor_sync(0xffffffffu, mx1, 2));
        float s0 = 0.f, s1 = 0.f;
#pragma unroll
        for (int nt = 0; nt < 7; nt++)
#pragma unroll
            for (int s = 0; s < 2; s++) {
                float e0 = __expf(lo[nt][s] - mx0);
                float e1 = __expf(hi[nt][s] - mx1);
                lo[nt][s] = e0; hi[nt][s] = e1;
                s0 += e0; s1 += e1;
            }
        s0 += __shfl_xor_sync(0xffffffffu, s0, 1); s0 += __shfl_xor_sync(0xffffffffu, s0, 2);
        s1 += __shfl_xor_sync(0xffffffffu, s1, 1); s1 += __shfl_xor_sync(0xffffffffu, s1, 2);
        const float i0 = 1.f / s0, i1 = 1.f / s1;
#pragma unroll
        for (int nt = 0; nt < 7; nt++) {
            lo[nt][0] *= i0; lo[nt][1] *= i0;
            hi[nt][0] *= i1; hi[nt][1] *= i1;
        }

        float o[4][4];
#pragma unroll
        for (int nf = 0; nf < 4; nf++)
#pragma unroll
            for (int e = 0; e < 4; e++) o[nf][e] = 0.f;
        const int sA = tig >> 1, sB = sA + 2;
        const bool od = (tig & 1);
#pragma unroll
        for (int kt = 0; kt < 7; kt++) {
            float l0a = __shfl_sync(0xffffffffu, lo[kt][0], sA, 4);
            float l1a = __shfl_sync(0xffffffffu, lo[kt][1], sA, 4);
            float l0b = __shfl_sync(0xffffffffu, lo[kt][0], sB, 4);
            float l1b = __shfl_sync(0xffffffffu, lo[kt][1], sB, 4);
            float h0a = __shfl_sync(0xffffffffu, hi[kt][0], sA, 4);
            float h1a = __shfl_sync(0xffffffffu, hi[kt][1], sA, 4);
            float h0b = __shfl_sync(0xffffffffu, hi[kt][0], sB, 4);
            float h1b = __shfl_sync(0xffffffffu, hi[kt][1], sB, 4);
            uint32_t ap[4];
            ap[0] = f2tf(od ? l1a : l0a);
            ap[1] = f2tf(od ? h1a : h0a);
            ap[2] = f2tf(od ? l1b : l0b);
            ap[3] = f2tf(od ? h1b : h0b);
#pragma unroll
            for (int nf = 0; nf < 4; nf++) {
                const float* vpt = qs + (kt * 8 + tig) * QS_LD + 256 + h * 32 + nf * 8 + gid;
                mma8(o[nf], ap, f2tf(vpt[0]), f2tf(vpt[4 * QS_LD]));
            }
        }
#pragma unroll
        for (int nf = 0; nf < 4; nf++) {
            const int col = h * 32 + nf * 8 + 2 * tig;
            if (v0) *(float2*)&g_ao[(row0 + r0) * DIM + col] = make_float2(o[nf][0], o[nf][1]);
            if (v1) *(float2*)&g_ao[(row0 + r1) * DIM + col] = make_float2(o[nf][2], o[nf][3]);
        }
    }
}

extern "C" void kernel_launch(void* const* d_in, const int* in_sizes, int n_in,
                              void* d_out, int out_size)
{
    const float* x      = (const float*)d_in[0];
    const float* mask   = (const float*)d_in[1];
    const float* w_qkv  = (const float*)d_in[2];
    const float* b_qkv  = (const float*)d_in[3];
    const float* btab   = (const float*)d_in[4];
    const float* w_proj = (const float*)d_in[5];
    const float* b_proj = (const float*)d_in[6];
    const int*   relidx = (const int*)  d_in[7];
    float* out = (float*)d_out;

    cudaFuncSetAttribute(gemm_k128<0>, cudaFuncAttributeMaxDynamicSharedMemorySize,
                         GEMM_SMEMF * 4);
    cudaFuncSetAttribute(gemm_k128<1>, cudaFuncAttributeMaxDynamicSharedMemorySize,
                         GEMM_SMEMF * 4);
    cudaFuncSetAttribute(attn_kernel, cudaFuncAttributeMaxDynamicSharedMemorySize,
                         ATTN_SMEMF * 4);

    prep_kernel<<<128, 512>>>(w_qkv, w_proj);
    gemm_k128<0><<<dim3(3136, 3), 256, GEMM_SMEMF * 4>>>(x, b_qkv, nullptr);
    attn_kernel<<<NWIN, 256, ATTN_SMEMF * 4>>>(mask, btab, relidx);
    gemm_k128<1><<<dim3(3136, 1), 256, GEMM_SMEMF * 4>>>(nullptr, b_proj, out);
}

// round 10
// speedup vs baseline: 1.6546x; 1.6226x over previous
#include <cuda_runtime.h>
#include <cstdint>

#define NTOK   49
#define DIM    128
#define NWIN   4096
#define SCALE  0.17677669529663687f

// ---- global scratch (static __device__, no allocation) ----
__device__ float g_wq[49152];         // w_qkv, tf32 B-frag-packed (lane-ordered)
__device__ float g_wp[16384];         // w_proj, tf32 B-frag-packed (lane-ordered)
__device__ float g_qkv[77070336];     // [200704][384]  Q(scaled)|K|V raw
__device__ float g_ao[25690112];      // [200704][128]  attention output raw

__device__ __forceinline__ uint32_t f2tf(float f) {
    uint32_t u;
    asm("cvt.rna.tf32.f32 %0, %1;" : "=r"(u) : "f"(f));
    return u;
}
__device__ __forceinline__ void mma8(float* c, const uint32_t* a, uint32_t b0, uint32_t b1) {
    asm("mma.sync.aligned.m16n8k8.row.col.f32.tf32.tf32.f32 "
        "{%0,%1,%2,%3},{%4,%5,%6,%7},{%8,%9},{%0,%1,%2,%3};"
        : "+f"(c[0]), "+f"(c[1]), "+f"(c[2]), "+f"(c[3])
        : "r"(a[0]), "r"(a[1]), "r"(a[2]), "r"(a[3]), "r"(b0), "r"(b1));
}
__device__ __forceinline__ void cpa16(uint32_t s, const void* g) {
    asm volatile("cp.async.cg.shared.global [%0], [%1], 16;" :: "r"(s), "l"(g));
}
__device__ __forceinline__ uint32_t smem_u32(const void* p) {
    uint32_t a;
    asm("{ .reg .u64 t; cvta.to.shared.u64 t, %1; cvt.u32.u64 %0, t; }" : "=r"(a) : "l"(p));
    return a;
}

// ---- prep: pack weights into tf32 B-fragment order (lane-ordered) ----
// float4 index = nt*512 + kt*32 + lane ; lane -> (gid = lane>>2, tig = lane&3)
// slot: {B[k][n], B[k+4][n], B[k][n+8], B[k+4][n+8]}, k = kt*8+tig, n = nt*16+gid
__global__ void prep_kernel(const float* __restrict__ wq, const float* __restrict__ wp) {
    int o = blockIdx.x * blockDim.x + threadIdx.x;        // 65536 total
    int oo = (o < 49152) ? o : o - 49152;
    int slot = oo & 3;
    int lane = (oo >> 2) & 31;
    int kt   = (oo >> 7) & 15;
    int nt   = oo >> 11;
    int tig = lane & 3, gid = lane >> 2;
    int k = kt * 8 + tig + 4 * (slot & 1);
    int n = nt * 16 + gid + 8 * (slot >> 1);
    if (o < 49152) g_wq[oo] = __uint_as_float(f2tf(wq[k * 384 + n]));
    else           g_wp[oo] = __uint_as_float(f2tf(wp[k * 128 + n]));
}

// ============================================================
// GEMM: C[64 x 128-slice] = A * B_packed + bias, K=128
//   A raw 64x128 loaded once, repacked in-smem to lane-ordered tf32 A-frags.
// MODE 0: A=x,    C=g_qkv (N=384, grid.y=3, Q slice scaled)
// MODE 1: A=g_ao, C=out   (N=128)
// ============================================================
#define GA_LD 132
#define GS_B  8448                 // raw A 64*132
#define GS_BS 24832
#define GEMM_SMEMF 24960           // 99840 B -> 2 blocks/SM

template<int MODE>
__global__ void __launch_bounds__(256, 2)
gemm_k128(const float* __restrict__ Aext, const float* __restrict__ bias,
          float* __restrict__ Cext)
{
    extern __shared__ float sm[];
    float* bs = sm + GS_BS;
    const int tid = threadIdx.x, wid = tid >> 5, lane = tid & 31;
    const int gid = lane >> 2, tig = lane & 3;
    const uint32_t su = smem_u32(sm);

    const float* A    = (MODE == 0) ? Aext : g_ao;
    const float* Bp   = (MODE == 0) ? (g_wq + blockIdx.y * 16384) : g_wp;
    const float* bptr = (MODE == 0) ? (bias + blockIdx.y * 128)   : bias;
    const int    NO   = (MODE == 0) ? 384 : 128;
    const int    cb   = (MODE == 0) ? blockIdx.y * 128 : 0;
    const float  sc   = (MODE == 0 && blockIdx.y == 0) ? SCALE : 1.f;

    const size_t arow0 = (size_t)blockIdx.x * 64;
    for (int i = tid; i < 2048; i += 256) {               // raw A 64x128
        int r = i >> 5, c4 = i & 31;
        cpa16(su + (r * GA_LD + c4 * 4) * 4, A + (arow0 + r) * DIM + c4 * 4);
    }
    for (int i = tid; i < 4096; i += 256)                 // B packed 16384 floats
        cpa16(su + (GS_B + i * 4) * 4, Bp + i * 4);
    if (tid < 128) bs[tid] = bptr[tid];
    asm volatile("cp.async.commit_group;\n\tcp.async.wait_group 0;");
    __syncthreads();

    // ---- one-time in-smem A repack, lane-ordered ----
    // float4 u: mt = u>>9, kt = (u>>5)&15, l = u&31 -> (gd = l>>2, tg = l&3)
    float4 stg[8];
#pragma unroll
    for (int j = 0; j < 8; j++) {
        const int u = tid + 256 * j;
        const int mt = u >> 9, kt = (u >> 5) & 15;
        const int l = u & 31, gd = (l >> 2) & 7, tg = l & 3;
        const int r = mt * 16 + gd, c = kt * 8 + tg;
        stg[j].x = __uint_as_float(f2tf(sm[r * GA_LD + c]));
        stg[j].y = __uint_as_float(f2tf(sm[(r + 8) * GA_LD + c]));
        stg[j].z = __uint_as_float(f2tf(sm[r * GA_LD + c + 4]));
        stg[j].w = __uint_as_float(f2tf(sm[(r + 8) * GA_LD + c + 4]));
    }
    __syncthreads();
    {
        float4* As4w = (float4*)sm;
#pragma unroll
        for (int j = 0; j < 8; j++) As4w[tid + 256 * j] = stg[j];
    }
    __syncthreads();

    const int mw = wid & 1, nw = wid >> 1;
    float c[2][4][4];
#pragma unroll
    for (int f = 0; f < 2; f++)
#pragma unroll
        for (int j = 0; j < 4; j++)
#pragma unroll
            for (int e = 0; e < 4; e++) c[f][j][e] = 0.f;

    const uint4* As4 = (const uint4*)sm;
    const uint4* Bs4 = (const uint4*)(sm + GS_B);
#pragma unroll
    for (int kt = 0; kt < 16; kt++) {
        uint4 av0 = As4[((mw * 2 + 0) * 16 + kt) * 32 + lane];
        uint4 av1 = As4[((mw * 2 + 1) * 16 + kt) * 32 + lane];
        uint4 bv0 = Bs4[((nw * 2 + 0) * 16 + kt) * 32 + lane];
        uint4 bv1 = Bs4[((nw * 2 + 1) * 16 + kt) * 32 + lane];
        mma8(c[0][0], (const uint32_t*)&av0, bv0.x, bv0.y);
        mma8(c[0][1], (const uint32_t*)&av0, bv0.z, bv0.w);
        mma8(c[0][2], (const uint32_t*)&av0, bv1.x, bv1.y);
        mma8(c[0][3], (const uint32_t*)&av0, bv1.z, bv1.w);
        mma8(c[1][0], (const uint32_t*)&av1, bv0.x, bv0.y);
        mma8(c[1][1], (const uint32_t*)&av1, bv0.z, bv0.w);
        mma8(c[1][2], (const uint32_t*)&av1, bv1.x, bv1.y);
        mma8(c[1][3], (const uint32_t*)&av1, bv1.z, bv1.w);
    }

    float* C = (MODE == 0) ? g_qkv : Cext;
#pragma unroll
    for (int f = 0; f < 2; f++) {
        const size_t r0 = arow0 + (mw * 2 + f) * 16 + gid;
#pragma unroll
        for (int j = 0; j < 4; j++) {
            const int cl = nw * 32 + j * 8 + 2 * tig;
            const float b0 = bs[cl], b1 = bs[cl + 1];
            const int cg = cb + cl;
            *(float2*)&C[r0 * NO + cg] =
                make_float2((c[f][j][0] + b0) * sc, (c[f][j][1] + b1) * sc);
            *(float2*)&C[(r0 + 8) * NO + cg] =
                make_float2((c[f][j][2] + b0) * sc, (c[f][j][3] + b1) * sc);
        }
    }
}

// ============================================================
// Attention: per-window, register softmax, shfl P-permute
// ============================================================
#define QS_LD 388
#define AS_RI 21728
#define AS_MK 24129
#define AS_BT 26530
#define ATTN_SMEMF 27206          // 108824 B

__global__ void __launch_bounds__(256, 2)
attn_kernel(const float* __restrict__ mask, const float* __restrict__ btab,
            const int* __restrict__ relidx)
{
    extern __shared__ float sm[];
    float* qs = sm;
    int*   ri = (int*)(sm + AS_RI);
    float* mk = sm + AS_MK;
    float* bt = sm + AS_BT;
    const int tid = threadIdx.x, wid = tid >> 5, lane = tid & 31;
    const int gid = lane >> 2, tig = lane & 3;
    const uint32_t su = smem_u32(sm);

    const int wb = blockIdx.x;
    const size_t row0 = (size_t)wb * NTOK;
    for (int i = tid; i < 4704; i += 256) {               // 49x384 float4
        int r = i / 96, c4 = i % 96;
        cpa16(su + (r * QS_LD + c4 * 4) * 4, g_qkv + (row0 + r) * 384 + c4 * 4);
    }
    for (int i = tid; i < 7 * QS_LD; i += 256) qs[49 * QS_LD + i] = 0.f;
    const int w = wb & 63;
    for (int i = tid; i < 2401; i += 256) { mk[i] = mask[w * 2401 + i]; ri[i] = relidx[i]; }
    for (int i = tid; i < 676; i += 256) bt[i] = btab[(i % 169) * 4 + (i / 169)];
    asm volatile("cp.async.commit_group;\n\tcp.async.wait_group 0;");
    __syncthreads();

    const int h = wid & 3, mt = wid >> 2;
#pragma unroll 1
    for (int sub = 0; sub < 2; sub++) {
        const int m0 = (mt * 2 + sub) * 16;
        const bool hiO = (m0 == 48);

        uint32_t aq[4][4];
#pragma unroll
        for (int kt = 0; kt < 4; kt++) {
            const float* p = qs + (m0 + gid) * QS_LD + h * 32 + kt * 8 + tig;
            aq[kt][0] = f2tf(p[0]);
            aq[kt][2] = f2tf(p[4]);
            aq[kt][1] = hiO ? 0u : f2tf(p[8 * QS_LD]);
            aq[kt][3] = hiO ? 0u : f2tf(p[8 * QS_LD + 4]);
        }
        float s_[7][4];
#pragma unroll
        for (int nt = 0; nt < 7; nt++) {
            float cc[4] = {0.f, 0.f, 0.f, 0.f};
#pragma unroll
            for (int kt = 0; kt < 4; kt++) {
                const float* kp = qs + (nt * 8 + gid) * QS_LD + 128 + h * 32 + kt * 8 + tig;
                mma8(cc, aq[kt], f2tf(kp[0]), f2tf(kp[4]));
            }
#pragma unroll
            for (int e = 0; e < 4; e++) s_[nt][e] = cc[e];
        }

        const int r0 = m0 + gid, r1 = r0 + 8;
        const bool v0 = r0 < NTOK, v1 = r1 < NTOK;
        float lo[7][2], hi[7][2];
        float mx0 = -1e30f, mx1 = -1e30f;
#pragma unroll
        for (int nt = 0; nt < 7; nt++)
#pragma unroll
            for (int s = 0; s < 2; s++) {
                const int cc = nt * 8 + 2 * tig + s;
                float a0 = -1e30f, a1 = -1e30f;
                if (cc < NTOK) {
                    if (v0) a0 = s_[nt][s]     + bt[h * 169 + ri[r0 * NTOK + cc]] + mk[r0 * NTOK + cc];
                    if (v1) a1 = s_[nt][2 + s] + bt[h * 169 + ri[r1 * NTOK + cc]] + mk[r1 * NTOK + cc];
                }
                lo[nt][s] = a0; hi[nt][s] = a1;
                mx0 = fmaxf(mx0, a0); mx1 = fmaxf(mx1, a1);
            }
        mx0 = fmaxf(mx0, __shfl_xor_sync(0xffffffffu, mx0, 1));
        mx0 = fmaxf(mx0, __shfl_xor_sync(0xffffffffu, mx0, 2));
        mx1 = fmaxf(mx1, __shfl_xor_sync(0xffffffffu, mx1, 1));
        mx1 = fmaxf(mx1, __shfl_xor_sync(0xffffffffu, mx1, 2));
        float s0 = 0.f, s1 = 0.f;
#pragma unroll
        for (int nt = 0; nt < 7; nt++)
#pragma unroll
            for (int s = 0; s < 2; s++) {
                float e0 = __expf(lo[nt][s] - mx0);
                float e1 = __expf(hi[nt][s] - mx1);
                lo[nt][s] = e0; hi[nt][s] = e1;
                s0 += e0; s1 += e1;
            }
        s0 += __shfl_xor_sync(0xffffffffu, s0, 1); s0 += __shfl_xor_sync(0xffffffffu, s0, 2);
        s1 += __shfl_xor_sync(0xffffffffu, s1, 1); s1 += __shfl_xor_sync(0xffffffffu, s1, 2);
        const float i0 = 1.f / s0, i1 = 1.f / s1;
#pragma unroll
        for (int nt = 0; nt < 7; nt++) {
            lo[nt][0] *= i0; lo[nt][1] *= i0;
            hi[nt][0] *= i1; hi[nt][1] *= i1;
        }

        float o[4][4];
#pragma unroll
        for (int nf = 0; nf < 4; nf++)
#pragma unroll
            for (int e = 0; e < 4; e++) o[nf][e] = 0.f;
        const int sA = tig >> 1, sB = sA + 2;
        const bool od = (tig & 1);
#pragma unroll
        for (int kt = 0; kt < 7; kt++) {
            float l0a = __shfl_sync(0xffffffffu, lo[kt][0], sA, 4);
            float l1a = __shfl_sync(0xffffffffu, lo[kt][1], sA, 4);
            float l0b = __shfl_sync(0xffffffffu, lo[kt][0], sB, 4);
            float l1b = __shfl_sync(0xffffffffu, lo[kt][1], sB, 4);
            float h0a = __shfl_sync(0xffffffffu, hi[kt][0], sA, 4);
            float h1a = __shfl_sync(0xffffffffu, hi[kt][1], sA, 4);
            float h0b = __shfl_sync(0xffffffffu, hi[kt][0], sB, 4);
            float h1b = __shfl_sync(0xffffffffu, hi[kt][1], sB, 4);
            uint32_t ap[4];
            ap[0] = f2tf(od ? l1a : l0a);
            ap[1] = f2tf(od ? h1a : h0a);
            ap[2] = f2tf(od ? l1b : l0b);
            ap[3] = f2tf(od ? h1b : h0b);
#pragma unroll
            for (int nf = 0; nf < 4; nf++) {
                const float* vpt = qs + (kt * 8 + tig) * QS_LD + 256 + h * 32 + nf * 8 + gid;
                mma8(o[nf], ap, f2tf(vpt[0]), f2tf(vpt[4 * QS_LD]));
            }
        }
#pragma unroll
        for (int nf = 0; nf < 4; nf++) {
            const int col = h * 32 + nf * 8 + 2 * tig;
            if (v0) *(float2*)&g_ao[(row0 + r0) * DIM + col] = make_float2(o[nf][0], o[nf][1]);
            if (v1) *(float2*)&g_ao[(row0 + r1) * DIM + col] = make_float2(o[nf][2], o[nf][3]);
        }
    }
}

extern "C" void kernel_launch(void* const* d_in, const int* in_sizes, int n_in,
                              void* d_out, int out_size)
{
    const float* x      = (const float*)d_in[0];
    const float* mask   = (const float*)d_in[1];
    const float* w_qkv  = (const float*)d_in[2];
    const float* b_qkv  = (const float*)d_in[3];
    const float* btab   = (const float*)d_in[4];
    const float* w_proj = (const float*)d_in[5];
    const float* b_proj = (const float*)d_in[6];
    const int*   relidx = (const int*)  d_in[7];
    float* out = (float*)d_out;

    cudaFuncSetAttribute(gemm_k128<0>, cudaFuncAttributeMaxDynamicSharedMemorySize,
                         GEMM_SMEMF * 4);
    cudaFuncSetAttribute(gemm_k128<1>, cudaFuncAttributeMaxDynamicSharedMemorySize,
                         GEMM_SMEMF * 4);
    cudaFuncSetAttribute(attn_kernel, cudaFuncAttributeMaxDynamicSharedMemorySize,
                         ATTN_SMEMF * 4);

    prep_kernel<<<128, 512>>>(w_qkv, w_proj);
    gemm_k128<0><<<dim3(3136, 3), 256, GEMM_SMEMF * 4>>>(x, b_qkv, nullptr);
    attn_kernel<<<NWIN, 256, ATTN_SMEMF * 4>>>(mask, btab, relidx);
    gemm_k128<1><<<dim3(3136, 1), 256, GEMM_SMEMF * 4>>>(nullptr, b_proj, out);
}

// round 11
// speedup vs baseline: 2.1091x; 1.2747x over previous
#include <cuda_runtime.h>
#include <cstdint>

#define NTOK   49
#define DIM    128
#define NWIN   4096
#define SCALE  0.17677669529663687f

// ---- global scratch (static __device__, no allocation) ----
__device__ float g_wq[49152];                      // w_qkv, tf32 B-frag-packed (lane-ordered)
__device__ float g_wp[16384];                      // w_proj, tf32 B-frag-packed
__device__ float g_qkv[77070336];                  // [200704][384]  Q(scaled)|K|V raw
__device__ float g_ao[25690112];                   // [200704][128]  attention output raw
__device__ __align__(16) uint16_t g_bm[652288];    // [64][4][49][52] bf16 bias+mask

__device__ __forceinline__ uint32_t f2tf(float f) {
    uint32_t u;
    asm("cvt.rna.tf32.f32 %0, %1;" : "=r"(u) : "f"(f));
    return u;
}
__device__ __forceinline__ void mma8(float* c, const uint32_t* a, uint32_t b0, uint32_t b1) {
    asm("mma.sync.aligned.m16n8k8.row.col.f32.tf32.tf32.f32 "
        "{%0,%1,%2,%3},{%4,%5,%6,%7},{%8,%9},{%0,%1,%2,%3};"
        : "+f"(c[0]), "+f"(c[1]), "+f"(c[2]), "+f"(c[3])
        : "r"(a[0]), "r"(a[1]), "r"(a[2]), "r"(a[3]), "r"(b0), "r"(b1));
}
__device__ __forceinline__ void cpa16(uint32_t s, const void* g) {
    asm volatile("cp.async.cg.shared.global [%0], [%1], 16;" :: "r"(s), "l"(g));
}
__device__ __forceinline__ uint32_t smem_u32(const void* p) {
    uint32_t a;
    asm("{ .reg .u64 t; cvta.to.shared.u64 t, %1; cvt.u32.u64 %0, t; }" : "=r"(a) : "l"(p));
    return a;
}
__device__ __forceinline__ uint16_t f2bf(float f) {
    uint32_t u = __float_as_uint(f);
    return (uint16_t)((u + 0x7fffu + ((u >> 16) & 1u)) >> 16);
}

// ---- prep: pack weights into tf32 B-fragment order (lane-ordered) ----
__global__ void prep_kernel(const float* __restrict__ wq, const float* __restrict__ wp) {
    int o = blockIdx.x * blockDim.x + threadIdx.x;        // 65536 total
    int oo = (o < 49152) ? o : o - 49152;
    int slot = oo & 3;
    int lane = (oo >> 2) & 31;
    int kt   = (oo >> 7) & 15;
    int nt   = oo >> 11;
    int tig = lane & 3, gid = lane >> 2;
    int k = kt * 8 + tig + 4 * (slot & 1);
    int n = nt * 16 + gid + 8 * (slot >> 1);
    if (o < 49152) g_wq[oo] = __uint_as_float(f2tf(wq[k * 384 + n]));
    else           g_wp[oo] = __uint_as_float(f2tf(wp[k * 128 + n]));
}

// ---- prep_bm: bm[w][h][r][c52] = btab[ri[r,c],h] + mask[w,r,c]  (bf16) ----
__global__ void prep_bm(const float* __restrict__ mask, const float* __restrict__ btab,
                        const int* __restrict__ relidx) {
    int o = blockIdx.x * blockDim.x + threadIdx.x;        // 652288 total
    if (o >= 652288) return;
    int c = o % 52;
    int t = o / 52;
    int r = t % 49; t /= 49;
    int h = t & 3;
    int w = t >> 2;
    float v = 0.f;
    if (c < 49)
        v = btab[relidx[r * 49 + c] * 4 + h] + mask[w * 2401 + r * 49 + c];
    g_bm[o] = f2bf(v);
}

// ============================================================
// GEMM: C[64 x NO] = A * B_packed + bias, K=128, NS slices of 128
//   A raw loaded+repacked ONCE; B slices streamed through one buffer,
//   next-slice cp.async overlapped with epilogue stores.
// MODE 0: A=x,    C=g_qkv (NO=384, NS=3, slice0 scaled)
// MODE 1: A=g_ao, C=out   (NO=128, NS=1)
// ============================================================
#define GA_LD 132
#define GS_B  8448
#define GS_BS 24832
#define GEMM_SMEMF 25216           // 100864 B -> 2 blocks/SM

template<int MODE>
__global__ void __launch_bounds__(256, 2)
gemm_k128(const float* __restrict__ Aext, const float* __restrict__ bias,
          float* __restrict__ Cext)
{
    extern __shared__ float sm[];
    float* bs = sm + GS_BS;
    const int tid = threadIdx.x, wid = tid >> 5, lane = tid & 31;
    const int gid = lane >> 2, tig = lane & 3;
    const uint32_t su = smem_u32(sm);

    const float* A  = (MODE == 0) ? Aext : g_ao;
    const float* Bp = (MODE == 0) ? g_wq : g_wp;
    const int    NO = (MODE == 0) ? 384 : 128;
    const int    NS = (MODE == 0) ? 3 : 1;
    float*       C  = (MODE == 0) ? g_qkv : Cext;

    const size_t arow0 = (size_t)blockIdx.x * 64;
    for (int i = tid; i < 2048; i += 256) {               // raw A 64x128
        int r = i >> 5, c4 = i & 31;
        cpa16(su + (r * GA_LD + c4 * 4) * 4, A + (arow0 + r) * DIM + c4 * 4);
    }
    for (int i = tid; i < NO / 4; i += 256)               // bias
        cpa16(su + (GS_BS + i * 4) * 4, bias + i * 4);
    asm volatile("cp.async.commit_group;");               // group: A + bias
    for (int i = tid; i < 4096; i += 256)                 // B slice 0
        cpa16(su + (GS_B + i * 4) * 4, Bp + i * 4);
    asm volatile("cp.async.commit_group;");               // group: B0
    asm volatile("cp.async.wait_group 1;");               // A + bias ready
    __syncthreads();

    // ---- one-time in-smem A repack, lane-ordered ----
    float4 stg[8];
#pragma unroll
    for (int j = 0; j < 8; j++) {
        const int u = tid + 256 * j;
        const int mt = u >> 9, kt = (u >> 5) & 15;
        const int l = u & 31, gd = (l >> 2) & 7, tg = l & 3;
        const int r = mt * 16 + gd, c = kt * 8 + tg;
        stg[j].x = __uint_as_float(f2tf(sm[r * GA_LD + c]));
        stg[j].y = __uint_as_float(f2tf(sm[(r + 8) * GA_LD + c]));
        stg[j].z = __uint_as_float(f2tf(sm[r * GA_LD + c + 4]));
        stg[j].w = __uint_as_float(f2tf(sm[(r + 8) * GA_LD + c + 4]));
    }
    __syncthreads();
    {
        float4* As4w = (float4*)sm;
#pragma unroll
        for (int j = 0; j < 8; j++) As4w[tid + 256 * j] = stg[j];
    }
    asm volatile("cp.async.wait_group 0;");               // B0 ready
    __syncthreads();

    const int mw = wid & 1, nw = wid >> 1;
    const uint4* As4 = (const uint4*)sm;
    const uint4* Bs4 = (const uint4*)(sm + GS_B);

#pragma unroll 1
    for (int t = 0; t < NS; t++) {
        float c[2][4][4];
#pragma unroll
        for (int f = 0; f < 2; f++)
#pragma unroll
            for (int j = 0; j < 4; j++)
#pragma unroll
                for (int e = 0; e < 4; e++) c[f][j][e] = 0.f;

#pragma unroll
        for (int kt = 0; kt < 16; kt++) {
            uint4 av0 = As4[((mw * 2 + 0) * 16 + kt) * 32 + lane];
            uint4 av1 = As4[((mw * 2 + 1) * 16 + kt) * 32 + lane];
            uint4 bv0 = Bs4[((nw * 2 + 0) * 16 + kt) * 32 + lane];
            uint4 bv1 = Bs4[((nw * 2 + 1) * 16 + kt) * 32 + lane];
            mma8(c[0][0], (const uint32_t*)&av0, bv0.x, bv0.y);
            mma8(c[0][1], (const uint32_t*)&av0, bv0.z, bv0.w);
            mma8(c[0][2], (const uint32_t*)&av0, bv1.x, bv1.y);
            mma8(c[0][3], (const uint32_t*)&av0, bv1.z, bv1.w);
            mma8(c[1][0], (const uint32_t*)&av1, bv0.x, bv0.y);
            mma8(c[1][1], (const uint32_t*)&av1, bv0.z, bv0.w);
            mma8(c[1][2], (const uint32_t*)&av1, bv1.x, bv1.y);
            mma8(c[1][3], (const uint32_t*)&av1, bv1.z, bv1.w);
        }

        __syncthreads();                                  // all reads of Bs done
        if (t + 1 < NS) {                                 // prefetch next B slice
            const float* Bn = Bp + (t + 1) * 16384;
            for (int i = tid; i < 4096; i += 256)
                cpa16(su + (GS_B + i * 4) * 4, Bn + i * 4);
            asm volatile("cp.async.commit_group;");
        }

        // epilogue (overlaps next-slice B load)
        const int   cb = t * 128;
        const float sc = (MODE == 0 && t == 0) ? SCALE : 1.f;
#pragma unroll
        for (int f = 0; f < 2; f++) {
            const size_t r0 = arow0 + (mw * 2 + f) * 16 + gid;
#pragma unroll
            for (int j = 0; j < 4; j++) {
                const int cl = nw * 32 + j * 8 + 2 * tig;
                const float b0 = bs[cb + cl], b1 = bs[cb + cl + 1];
                const int cg = cb + cl;
                *(float2*)&C[r0 * NO + cg] =
                    make_float2((c[f][j][0] + b0) * sc, (c[f][j][1] + b1) * sc);
                *(float2*)&C[(r0 + 8) * NO + cg] =
                    make_float2((c[f][j][2] + b0) * sc, (c[f][j][3] + b1) * sc);
            }
        }
        if (t + 1 < NS) {
            asm volatile("cp.async.wait_group 0;");
            __syncthreads();
        }
    }
}

// ============================================================
// Attention: per-window, register softmax (bf16 fused bias+mask)
// ============================================================
#define QS_LD 388
#define AS_BM 21728                // uint32 view: 2548 words = 5096 floats
#define ATTN_SMEMF 26824           // 107296 B -> 2 blocks/SM

__global__ void __launch_bounds__(256, 2)
attn_kernel(int dummy)
{
    extern __shared__ float sm[];
    float* qs = sm;
    const uint32_t* bm32 = (const uint32_t*)(sm + AS_BM);
    const int tid = threadIdx.x, wid = tid >> 5, lane = tid & 31;
    const int gid = lane >> 2, tig = lane & 3;
    const uint32_t su = smem_u32(sm);

    const int wb = blockIdx.x;
    const size_t row0 = (size_t)wb * NTOK;
    for (int i = tid; i < 4704; i += 256) {               // 49x384 float4
        int r = i / 96, c4 = i % 96;
        cpa16(su + (r * QS_LD + c4 * 4) * 4, g_qkv + (row0 + r) * 384 + c4 * 4);
    }
    const int w = wb & 63;
    {
        const char* bsrc = (const char*)g_bm + (size_t)w * 20384;
        for (int i = tid; i < 1274; i += 256)             // bm slice 20384 B
            cpa16(su + AS_BM * 4 + i * 16, bsrc + i * 16);
    }
    for (int i = tid; i < 7 * QS_LD; i += 256) qs[49 * QS_LD + i] = 0.f;
    asm volatile("cp.async.commit_group;\n\tcp.async.wait_group 0;");
    __syncthreads();

    const int h = wid & 3, mt = wid >> 2;
#pragma unroll 1
    for (int sub = 0; sub < 2; sub++) {
        const int m0 = (mt * 2 + sub) * 16;
        const bool hiO = (m0 == 48);

        uint32_t aq[4][4];
#pragma unroll
        for (int kt = 0; kt < 4; kt++) {
            const float* p = qs + (m0 + gid) * QS_LD + h * 32 + kt * 8 + tig;
            aq[kt][0] = f2tf(p[0]);
            aq[kt][2] = f2tf(p[4]);
            aq[kt][1] = hiO ? 0u : f2tf(p[8 * QS_LD]);
            aq[kt][3] = hiO ? 0u : f2tf(p[8 * QS_LD + 4]);
        }
        float s_[7][4];
#pragma unroll
        for (int nt = 0; nt < 7; nt++) {
            float cc[4] = {0.f, 0.f, 0.f, 0.f};
#pragma unroll
            for (int kt = 0; kt < 4; kt++) {
                const float* kp = qs + (nt * 8 + gid) * QS_LD + 128 + h * 32 + kt * 8 + tig;
                mma8(cc, aq[kt], f2tf(kp[0]), f2tf(kp[4]));
            }
#pragma unroll
            for (int e = 0; e < 4; e++) s_[nt][e] = cc[e];
        }

        const int r0 = m0 + gid, r1 = r0 + 8;
        const bool v0 = r0 < NTOK, v1 = r1 < NTOK;
        const int br0 = (h * 49 + (v0 ? r0 : 0)) * 26;
        const int br1 = (h * 49 + (v1 ? r1 : 0)) * 26;
        float lo[7][2], hi[7][2];
        float mx0 = -1e30f, mx1 = -1e30f;
#pragma unroll
        for (int nt = 0; nt < 7; nt++) {
            const int cc0 = nt * 8 + 2 * tig;
            const uint32_t bv0 = bm32[br0 + nt * 4 + tig];
            const uint32_t bv1 = bm32[br1 + nt * 4 + tig];
            const float b00 = __uint_as_float(bv0 << 16);
            const float b01 = __uint_as_float(bv0 & 0xffff0000u);
            const float b10 = __uint_as_float(bv1 << 16);
            const float b11 = __uint_as_float(bv1 & 0xffff0000u);
            lo[nt][0] = (v0 && cc0     < NTOK) ? s_[nt][0] + b00 : -1e30f;
            lo[nt][1] = (v0 && cc0 + 1 < NTOK) ? s_[nt][1] + b01 : -1e30f;
            hi[nt][0] = (v1 && cc0     < NTOK) ? s_[nt][2] + b10 : -1e30f;
            hi[nt][1] = (v1 && cc0 + 1 < NTOK) ? s_[nt][3] + b11 : -1e30f;
            mx0 = fmaxf(mx0, fmaxf(lo[nt][0], lo[nt][1]));
            mx1 = fmaxf(mx1, fmaxf(hi[nt][0], hi[nt][1]));
        }
        mx0 = fmaxf(mx0, __shfl_xor_sync(0xffffffffu, mx0, 1));
        mx0 = fmaxf(mx0, __shfl_xor_sync(0xffffffffu, mx0, 2));
        mx1 = fmaxf(mx1, __shfl_xor_sync(0xffffffffu, mx1, 1));
        mx1 = fmaxf(mx1, __shfl_xor_sync(0xffffffffu, mx1, 2));
        float s0 = 0.f, s1 = 0.f;
#pragma unroll
        for (int nt = 0; nt < 7; nt++)
#pragma unroll
            for (int s = 0; s < 2; s++) {
                float e0 = __expf(lo[nt][s] - mx0);
                float e1 = __expf(hi[nt][s] - mx1);
                lo[nt][s] = e0; hi[nt][s] = e1;
                s0 += e0; s1 += e1;
            }
        s0 += __shfl_xor_sync(0xffffffffu, s0, 1); s0 += __shfl_xor_sync(0xffffffffu, s0, 2);
        s1 += __shfl_xor_sync(0xffffffffu, s1, 1); s1 += __shfl_xor_sync(0xffffffffu, s1, 2);
        const float i0 = 1.f / s0, i1 = 1.f / s1;
#pragma unroll
        for (int nt = 0; nt < 7; nt++) {
            lo[nt][0] *= i0; lo[nt][1] *= i0;
            hi[nt][0] *= i1; hi[nt][1] *= i1;
        }

        float o[4][4];
#pragma unroll
        for (int nf = 0; nf < 4; nf++)
#pragma unroll
            for (int e = 0; e < 4; e++) o[nf][e] = 0.f;
        const int sA = tig >> 1, sB = sA + 2;
        const bool od = (tig & 1);
#pragma unroll
        for (int kt = 0; kt < 7; kt++) {
            float l0a = __shfl_sync(0xffffffffu, lo[kt][0], sA, 4);
            float l1a = __shfl_sync(0xffffffffu, lo[kt][1], sA, 4);
            float l0b = __shfl_sync(0xffffffffu, lo[kt][0], sB, 4);
            float l1b = __shfl_sync(0xffffffffu, lo[kt][1], sB, 4);
            float h0a = __shfl_sync(0xffffffffu, hi[kt][0], sA, 4);
            float h1a = __shfl_sync(0xffffffffu, hi[kt][1], sA, 4);
            float h0b = __shfl_sync(0xffffffffu, hi[kt][0], sB, 4);
            float h1b = __shfl_sync(0xffffffffu, hi[kt][1], sB, 4);
            uint32_t ap[4];
            ap[0] = f2tf(od ? l1a : l0a);
            ap[1] = f2tf(od ? h1a : h0a);
            ap[2] = f2tf(od ? l1b : l0b);
            ap[3] = f2tf(od ? h1b : h0b);
#pragma unroll
            for (int nf = 0; nf < 4; nf++) {
                const float* vpt = qs + (kt * 8 + tig) * QS_LD + 256 + h * 32 + nf * 8 + gid;
                mma8(o[nf], ap, f2tf(vpt[0]), f2tf(vpt[4 * QS_LD]));
            }
        }
#pragma unroll
        for (int nf = 0; nf < 4; nf++) {
            const int col = h * 32 + nf * 8 + 2 * tig;
            if (v0) *(float2*)&g_ao[(row0 + r0) * DIM + col] = make_float2(o[nf][0], o[nf][1]);
            if (v1) *(float2*)&g_ao[(row0 + r1) * DIM + col] = make_float2(o[nf][2], o[nf][3]);
        }
    }
}

extern "C" void kernel_launch(void* const* d_in, const int* in_sizes, int n_in,
                              void* d_out, int out_size)
{
    const float* x      = (const float*)d_in[0];
    const float* mask   = (const float*)d_in[1];
    const float* w_qkv  = (const float*)d_in[2];
    const float* b_qkv  = (const float*)d_in[3];
    const float* btab   = (const float*)d_in[4];
    const float* w_proj = (const float*)d_in[5];
    const float* b_proj = (const float*)d_in[6];
    const int*   relidx = (const int*)  d_in[7];
    float* out = (float*)d_out;

    cudaFuncSetAttribute(gemm_k128<0>, cudaFuncAttributeMaxDynamicSharedMemorySize,
                         GEMM_SMEMF * 4);
    cudaFuncSetAttribute(gemm_k128<1>, cudaFuncAttributeMaxDynamicSharedMemorySize,
                         GEMM_SMEMF * 4);
    cudaFuncSetAttribute(attn_kernel, cudaFuncAttributeMaxDynamicSharedMemorySize,
                         ATTN_SMEMF * 4);

    prep_kernel<<<128, 512>>>(w_qkv, w_proj);
    prep_bm<<<1274, 512>>>(mask, btab, relidx);
    gemm_k128<0><<<3136, 256, GEMM_SMEMF * 4>>>(x, b_qkv, nullptr);
    attn_kernel<<<NWIN, 256, ATTN_SMEMF * 4>>>(0);
    gemm_k128<1><<<3136, 256, GEMM_SMEMF * 4>>>(nullptr, b_proj, out);
}